// round 1
// baseline (speedup 1.0000x reference)
#include <cuda_runtime.h>
#include <math_constants.h>
#include <cstdint>

#define D_DIM     256
#define M_TILE    64
#define N_TILE    128
#define K_TILE    32
#define XS_STRIDE 68      // 64 rows + 4 pad (float4-aligned, conflict-spread)
#define ES_STRIDE 132     // 128 codes + 4 pad
#define NTHREADS  256
#define MAX_CODES 16384

__device__ float  g_enorm2[MAX_CODES];
__device__ double g_loss_sum;

__global__ void vq_zero() { g_loss_sum = 0.0; }

// ||e||^2 per code, one warp per code (order-free thanks to the lattice-shift argument:
// en ~1e-6 only perturbs the final add at magnitude ~256 near rounding boundaries).
__global__ void vq_enorm(const float* __restrict__ emb, int ncodes) {
    int warp = (blockIdx.x * blockDim.x + threadIdx.x) >> 5;
    int lane = threadIdx.x & 31;
    if (warp >= ncodes) return;
    const float* e = emb + (size_t)warp * D_DIM;
    float s = 0.f;
#pragma unroll
    for (int t = 0; t < D_DIM / 32; ++t) {
        float v = e[lane + t * 32];
        s = __fadd_rn(s, __fmul_rn(v, v));
    }
#pragma unroll
    for (int off = 16; off; off >>= 1)
        s = __fadd_rn(s, __shfl_xor_sync(0xffffffffu, s, off));
    if (lane == 0) g_enorm2[warp] = s;
}

// Fused: fp32 GEMM scores + exact-formula dist + argmin(first-index ties) +
// y = fl(x + fl(q - x)) + loss partial sums.
__global__ void __launch_bounds__(NTHREADS, 1)
vq_main(const float* __restrict__ x, const float* __restrict__ emb,
        float* __restrict__ y_out, float* __restrict__ idx_out,
        int BT, int ncodes)
{
    extern __shared__ float smem[];
    float*  xs = smem;                                  // D_DIM * XS_STRIDE (x tile, transposed)
    float*  es = xs + D_DIM * XS_STRIDE;                // 2 * K_TILE * ES_STRIDE (double buffer)
    float*  xn = es + 2 * K_TILE * ES_STRIDE;           // M_TILE
    float*  bd = xn + M_TILE;                           // M_TILE * 16
    int*    bi = (int*)(bd + M_TILE * 16);              // M_TILE * 16
    double* warp_loss = (double*)(bi + M_TILE * 16);    // NTHREADS/32

    const int tid  = threadIdx.x;
    const int row0 = blockIdx.x * M_TILE;

    // Load x tile transposed: xs[k][r]
    for (int i = tid; i < M_TILE * D_DIM; i += NTHREADS) {
        int r = i >> 8;
        int k = i & (D_DIM - 1);
        int gr = row0 + r;
        xs[k * XS_STRIDE + r] = (gr < BT) ? x[(size_t)gr * D_DIM + k] : 0.f;
    }
    __syncthreads();

    // ||f||^2 per row (order-free, lattice-shift argument)
    if (tid < M_TILE) {
        float s = 0.f;
#pragma unroll 8
        for (int k = 0; k < D_DIM; ++k) {
            float v = xs[k * XS_STRIDE + tid];
            s = __fadd_rn(s, __fmul_rn(v, v));
        }
        xn[tid] = s;
    }
    __syncthreads();

    const int ty = tid >> 4;   // 0..15 (row groups of 4)
    const int tx = tid & 15;   // 0..15 (code groups of 8)
    float axn[4];
#pragma unroll
    for (int i = 0; i < 4; ++i) axn[i] = xn[ty * 4 + i];

    float bestd[4]; int besti[4];
#pragma unroll
    for (int i = 0; i < 4; ++i) { bestd[i] = CUDART_INF_F; besti[i] = 0; }

    // emb staging map: thread -> (code lc in tile, kk-halves lp)
    const int lc = tid >> 1;
    const int lp = (tid & 1) * 16;

    const int n_chunks = ncodes / N_TILE;
    for (int nc = 0; nc < n_chunks; ++nc) {
        const int n0 = nc * N_TILE;
        const float* esrc = emb + (size_t)(n0 + lc) * D_DIM + lp;

        float acc[4][8];
#pragma unroll
        for (int i = 0; i < 4; ++i)
#pragma unroll
            for (int j = 0; j < 8; ++j) acc[i][j] = 0.f;

        // prologue: k-chunk 0 -> buffer 0
        {
            float4 st0 = *(const float4*)(esrc + 0);
            float4 st1 = *(const float4*)(esrc + 4);
            float4 st2 = *(const float4*)(esrc + 8);
            float4 st3 = *(const float4*)(esrc + 12);
            float4 st[4] = {st0, st1, st2, st3};
#pragma unroll
            for (int j = 0; j < 4; ++j) {
                es[(lp + j * 4 + 0) * ES_STRIDE + lc] = st[j].x;
                es[(lp + j * 4 + 1) * ES_STRIDE + lc] = st[j].y;
                es[(lp + j * 4 + 2) * ES_STRIDE + lc] = st[j].z;
                es[(lp + j * 4 + 3) * ES_STRIDE + lc] = st[j].w;
            }
        }
        __syncthreads();

#pragma unroll 1
        for (int kc = 0; kc < D_DIM / K_TILE; ++kc) {
            // prefetch next k-chunk into registers (overlaps with FMA work)
            float4 s0, s1, s2, s3;
            const bool hn = (kc + 1 < D_DIM / K_TILE);
            if (hn) {
                const float* p = esrc + (kc + 1) * K_TILE;
                s0 = *(const float4*)(p + 0);
                s1 = *(const float4*)(p + 4);
                s2 = *(const float4*)(p + 8);
                s3 = *(const float4*)(p + 12);
            }
            const float* ec = es + (kc & 1) * (K_TILE * ES_STRIDE);
            const float* xc = xs + kc * K_TILE * XS_STRIDE;
#pragma unroll 8
            for (int kk = 0; kk < K_TILE; ++kk) {
                float4 a  = *(const float4*)(xc + kk * XS_STRIDE + ty * 4);
                float4 b0 = *(const float4*)(ec + kk * ES_STRIDE + tx * 8);
                float4 b1 = *(const float4*)(ec + kk * ES_STRIDE + tx * 8 + 4);
                float av[4] = {a.x, a.y, a.z, a.w};
                float bv[8] = {b0.x, b0.y, b0.z, b0.w, b1.x, b1.y, b1.z, b1.w};
#pragma unroll
                for (int i = 0; i < 4; ++i)
#pragma unroll
                    for (int j = 0; j < 8; ++j)
                        acc[i][j] = __fmaf_rn(av[i], bv[j], acc[i][j]);
            }
            if (hn) {
                __syncthreads();
                float* dst = es + ((kc + 1) & 1) * (K_TILE * ES_STRIDE);
                float4 st[4] = {s0, s1, s2, s3};
#pragma unroll
                for (int j = 0; j < 4; ++j) {
                    dst[(lp + j * 4 + 0) * ES_STRIDE + lc] = st[j].x;
                    dst[(lp + j * 4 + 1) * ES_STRIDE + lc] = st[j].y;
                    dst[(lp + j * 4 + 2) * ES_STRIDE + lc] = st[j].z;
                    dst[(lp + j * 4 + 3) * ES_STRIDE + lc] = st[j].w;
                }
                __syncthreads();
            }
        }

        // Epilogue: exact reference formula dist = fl(fl(xn - 2*dot) + en).
        // Codes strictly increase per thread -> strict '<' keeps first index.
#pragma unroll
        for (int j = 0; j < 8; ++j) {
            int code = n0 + tx * 8 + j;
            float en = g_enorm2[code];
#pragma unroll
            for (int i = 0; i < 4; ++i) {
                float dist = __fadd_rn(__fsub_rn(axn[i], __fmul_rn(2.0f, acc[i][j])), en);
                if (dist < bestd[i]) { bestd[i] = dist; besti[i] = code; }
            }
        }
    }

    // Cross-thread (tx) argmin per row with (dist, idx) lexicographic tie-break
#pragma unroll
    for (int i = 0; i < 4; ++i) {
        bd[(ty * 4 + i) * 16 + tx] = bestd[i];
        bi[(ty * 4 + i) * 16 + tx] = besti[i];
    }
    __syncthreads();
    if (tid < M_TILE) {
        float d0 = bd[tid * 16]; int i0 = bi[tid * 16];
#pragma unroll
        for (int t = 1; t < 16; ++t) {
            float d = bd[tid * 16 + t]; int ii = bi[tid * 16 + t];
            if (d < d0 || (d == d0 && ii < i0)) { d0 = d; i0 = ii; }
        }
        bi[tid * 16] = i0;
        if (idx_out != nullptr && (row0 + tid) < BT)
            idx_out[row0 + tid] = (float)i0;
    }
    __syncthreads();

    // y = fl(x + fl(q - x)), loss += fl(q-x)^2
    float lsum = 0.f;
    for (int i = tid; i < M_TILE * D_DIM; i += NTHREADS) {
        int r = i >> 8;
        int k = i & (D_DIM - 1);
        int gr = row0 + r;
        if (gr < BT) {
            int code = bi[r * 16];
            float xv = xs[k * XS_STRIDE + r];
            float q  = __ldg(&emb[(size_t)code * D_DIM + k]);
            float df = __fsub_rn(q, xv);
            y_out[(size_t)gr * D_DIM + k] = __fadd_rn(xv, df);
            lsum = __fmaf_rn(df, df, lsum);
        }
    }
#pragma unroll
    for (int off = 16; off; off >>= 1)
        lsum += __shfl_xor_sync(0xffffffffu, lsum, off);
    if ((tid & 31) == 0) warp_loss[tid >> 5] = (double)lsum;
    __syncthreads();
    if (tid == 0) {
        double t = 0.0;
#pragma unroll
        for (int w = 0; w < NTHREADS / 32; ++w) t += warp_loss[w];
        atomicAdd(&g_loss_sum, t);
    }
}

__global__ void vq_finalize(float* __restrict__ loss_out, double inv_n) {
    loss_out[0] = (float)(g_loss_sum * inv_n);
}

extern "C" void kernel_launch(void* const* d_in, const int* in_sizes, int n_in,
                              void* d_out, int out_size)
{
    // x is the big tensor, emb the small one (defensive against ordering)
    int xi = 0, ei = 1;
    if (n_in >= 2 && in_sizes[1] > in_sizes[0]) { xi = 1; ei = 0; }
    const float* x   = (const float*)d_in[xi];
    const float* emb = (const float*)d_in[ei];
    const int BT     = in_sizes[xi] / D_DIM;     // 65536
    const int ncodes = in_sizes[ei] / D_DIM;     // 8192

    float* out = (float*)d_out;
    const long long yN = (long long)BT * D_DIM;
    float* idxp = ((long long)out_size >= yN + BT) ? out + yN : nullptr;
    const bool has_loss = ((long long)out_size >= yN + BT + 1);

    const size_t SMEM =
        (size_t)(D_DIM * XS_STRIDE + 2 * K_TILE * ES_STRIDE + M_TILE + M_TILE * 16) * sizeof(float)
        + (size_t)(M_TILE * 16) * sizeof(int)
        + (NTHREADS / 32) * sizeof(double);
    cudaFuncSetAttribute((const void*)vq_main,
                         cudaFuncAttributeMaxDynamicSharedMemorySize, (int)SMEM);

    vq_zero<<<1, 1>>>();
    vq_enorm<<<(ncodes * 32 + NTHREADS - 1) / NTHREADS, NTHREADS>>>(emb, ncodes);
    const int grid = (BT + M_TILE - 1) / M_TILE;
    vq_main<<<grid, NTHREADS, SMEM>>>(x, emb, out, idxp, BT, ncodes);
    if (has_loss)
        vq_finalize<<<1, 1>>>(out + yN + BT, 1.0 / ((double)BT * (double)D_DIM));
}